// round 15
// baseline (speedup 1.0000x reference)
#include <cuda_runtime.h>
#include <cuda_fp16.h>
#include <cstdint>

#define NN 100000
#define EE 3200000
#define HD 64
#define BN_EPS 1e-5f
#define NSCAN ((NN + 1023) / 1024)   // 98 scan blocks
#define GW 4                          // warps per gather block
#define CHUNK 16                      // edges per staged chunk
#define GBLK 1924                     // 13 blocks/SM -> 7696 warps

// ---------------- scratch (device globals; no allocation allowed) ----------------
__device__ float g_deg[NN];
__device__ int   g_cnt[NN];
__device__ int   g_rowptr[NN + 1];
__device__ int   g_cursor[NN];
__device__ int   g_bsum[NSCAN];
__device__ int   g_boff[NSCAN];
__device__ __align__(8)  int2   g_edges[EE];     // {src*128 byte-offset, coef_bits}
__device__ __align__(16) __half g_bufh[NN * HD];
__device__ __align__(16) float  g_buf1[NN * HD];
__device__ __align__(16) float  g_buf2[NN * HD];
__device__ float g_stats[6 * HD];
__device__ float g_W2f[HD * HD];
__device__ float g_cb2[HD];
__device__ float g_W3f[HD * HD];
__device__ float g_d3[HD];
__device__ __align__(16) float g_wfbf[HD + 4];

// ---------------- graph prep ----------------

__global__ void init_k(float* deg, int* cnt, float* stats) {
    int i = blockIdx.x * blockDim.x + threadIdx.x;
    if (i < NN) { deg[i] = 1.0f; cnt[i] = 0; }
    if (i < 6 * HD) stats[i] = 0.0f;
}

__global__ void deghist_k(const int* __restrict__ ei, const float* __restrict__ ew,
                          float* deg, int* cnt) {
    int e = blockIdx.x * blockDim.x + threadIdx.x;
    if (e >= EE) return;
    int d = ei[EE + e];
    atomicAdd(&deg[d], ew[e]);
    atomicAdd(&cnt[d], 1);
}

__global__ void scan1_k(const int* __restrict__ cnt, int* rowptr, int* bsum) {
    __shared__ int sh[1024];
    int t = threadIdx.x;
    int i = blockIdx.x * 1024 + t;
    int c = (i < NN) ? cnt[i] : 0;
    sh[t] = c;
    __syncthreads();
#pragma unroll
    for (int off = 1; off < 1024; off <<= 1) {
        int v = (t >= off) ? sh[t - off] : 0;
        __syncthreads();
        sh[t] += v;
        __syncthreads();
    }
    if (i < NN) rowptr[i] = sh[t] - c;
    if (t == 1023) bsum[blockIdx.x] = sh[t];
}

__global__ void scan2_k(const int* __restrict__ bsum, int* boff, int* rowptr) {
    int lane = threadIdx.x;
    int run = 0;
    for (int b0 = 0; b0 < NSCAN; b0 += 32) {
        int idx = b0 + lane;
        int c = (idx < NSCAN) ? bsum[idx] : 0;
        int v = c;
#pragma unroll
        for (int off = 1; off < 32; off <<= 1) {
            int t = __shfl_up_sync(0xFFFFFFFFu, v, off);
            if (lane >= off) v += t;
        }
        if (idx < NSCAN) boff[idx] = run + v - c;
        run += __shfl_sync(0xFFFFFFFFu, v, 31);
    }
    if (lane == 0) rowptr[NN] = EE;
}

__global__ void scan3_k(int* rowptr, const int* __restrict__ boff, int* cursor) {
    int i = blockIdx.x * blockDim.x + threadIdx.x;
    if (i >= NN) return;
    int v = rowptr[i] + boff[i >> 10];
    rowptr[i] = v;
    cursor[i] = v;
}

__global__ void fill_k(const int* __restrict__ ei, const float* __restrict__ ew,
                       const float* __restrict__ deg, int* cursor, int2* edges) {
    int e = blockIdx.x * blockDim.x + threadIdx.x;
    if (e >= EE) return;
    int s = ei[e];
    int d = ei[EE + e];
    float cf = ew[e] * rsqrtf(deg[s]) * rsqrtf(deg[d]);
    int pos = atomicAdd(&cursor[d], 1);
    edges[pos] = make_int2(s * 128, __float_as_int(cf));
}

// ---------------- GEMM: C[n,64] = A[n,K] @ W[K,64] (+ bias, + optional BN stats) ----
template <int K, bool HOUT>
__global__ void gemm_k(const float* __restrict__ A, const float* __restrict__ W,
                       const float* __restrict__ bias, float* __restrict__ C,
                       __half* __restrict__ Ch, float* __restrict__ stats, int n) {
    constexpr int TM = 64;
    constexpr int KC = 64;
    __shared__ float As[KC][TM + 4];
    __shared__ float Ws[KC][64];
    const int tid = threadIdx.x;
    const int tx = tid & 15;
    const int ty = tid >> 4;
    const int m_base = blockIdx.x * TM;

    float acc[4][4] = {};

    for (int kk = 0; kk < K; kk += KC) {
        for (int idx = tid; idx < TM * KC; idx += 256) {
            int m = idx / KC, k = idx % KC;
            int row = m_base + m;
            As[k][m] = (row < n) ? A[row * K + kk + k] : 0.0f;
        }
        for (int idx = tid; idx < KC * 64; idx += 256) {
            int k = idx >> 6, c = idx & 63;
            Ws[k][c] = W[(kk + k) * 64 + c];
        }
        __syncthreads();
#pragma unroll 16
        for (int k = 0; k < KC; k++) {
            float4 a = *(const float4*)&As[k][ty * 4];
            float4 b = *(const float4*)&Ws[k][tx * 4];
            float av[4] = {a.x, a.y, a.z, a.w};
            float bv[4] = {b.x, b.y, b.z, b.w};
#pragma unroll
            for (int i = 0; i < 4; i++)
#pragma unroll
                for (int j = 0; j < 4; j++)
                    acc[i][j] += av[i] * bv[j];
        }
        __syncthreads();
    }

#pragma unroll
    for (int i = 0; i < 4; i++) {
        int row = m_base + ty * 4 + i;
        bool ok = row < n;
#pragma unroll
        for (int j = 0; j < 4; j++) {
            float v = acc[i][j];
            if (bias) v += bias[tx * 4 + j];
            acc[i][j] = ok ? v : 0.0f;
        }
        if (!ok) continue;
        if (HOUT) {
            __half2* p = (__half2*)&Ch[row * 64 + tx * 4];
            p[0] = __float22half2_rn(make_float2(acc[i][0], acc[i][1]));
            p[1] = __float22half2_rn(make_float2(acc[i][2], acc[i][3]));
        } else {
            float4* p = (float4*)&C[row * 64 + tx * 4];
            *p = make_float4(acc[i][0], acc[i][1], acc[i][2], acc[i][3]);
        }
    }

    if (stats) {   // fused BN statistics; reuse dead As tile for the reduction
        float* sred = &As[0][0];        // [32][64]: rows 0-15 sums, 16-31 sq
#pragma unroll
        for (int j = 0; j < 4; j++) {
            float s = acc[0][j] + acc[1][j] + acc[2][j] + acc[3][j];
            float q = acc[0][j] * acc[0][j] + acc[1][j] * acc[1][j]
                    + acc[2][j] * acc[2][j] + acc[3][j] * acc[3][j];
            sred[ty * 64 + tx * 4 + j] = s;
            sred[(16 + ty) * 64 + tx * 4 + j] = q;
        }
        __syncthreads();
        if (tid < 64) {
            float s = 0.f, q = 0.f;
#pragma unroll
            for (int r = 0; r < 16; r++) {
                s += sred[r * 64 + tid];
                q += sred[(16 + r) * 64 + tid];
            }
            atomicAdd(&stats[tid], s);
            atomicAdd(&stats[64 + tid], q);
        }
    }
}

// ---------------- edge-stream gather, double-buffered cp.async row staging --------
// 16-edge chunks -> 16.6KB smem/block -> ~13 blocks/SM (~52 warps/SM).
__global__ void __launch_bounds__(GW * 32, 12)
gather_k(const __half2* __restrict__ inh, const int* __restrict__ rowptr,
         const int2* __restrict__ edges, const float* __restrict__ deg,
         const float* __restrict__ bias, float2* __restrict__ out2,
         float* __restrict__ stats, int relu, int npw) {
    __shared__ __align__(16) char rb[GW][2][CHUNK * 128];
    __shared__ float cfb[GW][2][CHUNK];

    const int w    = threadIdx.x >> 5;
    const int lane = threadIdx.x & 31;
    const int warp = (blockIdx.x * blockDim.x + threadIdx.x) >> 5;

    float s0 = 0.f, q0 = 0.f, s1 = 0.f, q1 = 0.f;
    const int n0 = warp * npw;

    if (n0 < NN) {
        const int n1 = min(NN, n0 + npw);
        const int estart = __ldg(&rowptr[n0]);
        const int eend   = __ldg(&rowptr[n1]);
        const int nch    = (eend - estart + CHUNK - 1) / CHUNK;

        float2 bv = relu ? ((const float2*)bias)[lane] : make_float2(0.f, 0.f);
        const char* inb = (const char*)inh;
        unsigned int rbs0 = (unsigned int)__cvta_generic_to_shared(&rb[w][0][0]);
        unsigned int rbs1 = (unsigned int)__cvta_generic_to_shared(&rb[w][1][0]);

        auto stage = [&](int c, int b) {
            int2 p = make_int2(0, 0);               // pad: row 0, coef 0
            if (lane < CHUNK) {
                int e = estart + c * CHUNK + lane;
                if (e < eend) p = __ldg(&edges[e]);
                cfb[w][b][lane] = __int_as_float(p.y);
            }
            unsigned int dstb = b ? rbs1 : rbs0;
#pragma unroll
            for (int j = 0; j < (CHUNK * 8) / 32; j++) {   // 4 cp.async/thread
                int seg = j * 32 + lane;            // 0..127
                int row = seg >> 3;                 // 0..15
                int ss  = seg & 7;
                int off = __shfl_sync(0xFFFFFFFFu, p.x, row);
                const char* src = inb + off + ss * 16;
                unsigned int dst = dstb + row * 128 + ss * 16;
                asm volatile("cp.async.cg.shared.global [%0], [%1], 16;"
                             :: "r"(dst), "l"(src));
            }
            asm volatile("cp.async.commit_group;");
        };

        int i = n0;
        int end = __ldg(&rowptr[i + 1]);
        float inv = __fdividef(1.0f, deg[i]);
        float2 sf = __half22float2(inh[i * 32 + lane]);
        float2 acc = make_float2(sf.x * inv, sf.y * inv);

        auto flush = [&](int node) {
            float2 o = acc;
            if (relu) {
                o.x = fmaxf(o.x + bv.x, 0.f);
                o.y = fmaxf(o.y + bv.y, 0.f);
            }
            out2[node * 32 + lane] = o;
            s0 += o.x; q0 += o.x * o.x;
            s1 += o.y; q1 += o.y * o.y;
        };
        auto initnode = [&](int node) {
            float iv = __fdividef(1.0f, deg[node]);
            float2 s = __half22float2(inh[node * 32 + lane]);
            acc = make_float2(s.x * iv, s.y * iv);
        };

        if (nch > 0) stage(0, 0);
        for (int c = 0; c < nch; c++) {
            if (c + 1 < nch) {
                stage(c + 1, (c + 1) & 1);
                asm volatile("cp.async.wait_group 1;");
            } else {
                asm volatile("cp.async.wait_group 0;");
            }
            __syncwarp();
            int b = c & 1;
            int base = estart + c * CHUNK;
            const char* rbc = &rb[w][b][0];
            const float* cfc = &cfb[w][b][0];
#pragma unroll
            for (int k = 0; k < CHUNK; k++) {
                int eg = base + k;
                while (eg >= end && i + 1 < n1) {
                    flush(i);
                    i++;
                    initnode(i);
                    end = __ldg(&rowptr[i + 1]);
                }
                float cf = cfc[k];
                __half2 hv = *(const __half2*)(rbc + k * 128 + lane * 4);
                float2 v = __half22float2(hv);
                acc.x += cf * v.x;
                acc.y += cf * v.y;
            }
            __syncwarp();
        }
        flush(i);
        for (int j = i + 1; j < n1; j++) { initnode(j); flush(j); }
    }

    atomicAdd(&stats[2 * lane],          s0);
    atomicAdd(&stats[2 * lane + 1],      s1);
    atomicAdd(&stats[64 + 2 * lane],     q0);
    atomicAdd(&stats[64 + 2 * lane + 1], q1);
}

// ---------------- BN folds ----------------
__global__ void fold_k(const float* __restrict__ stats, const float* __restrict__ g,
                       const float* __restrict__ beta, const float* __restrict__ Wn,
                       const float* __restrict__ bn, float* __restrict__ Wf,
                       float* __restrict__ bf, int add_bn) {
    __shared__ float a[64], c[64];
    int t = threadIdx.x;
    if (t < 64) {
        float mean = stats[t] * (1.0f / NN);
        float var = stats[64 + t] * (1.0f / NN) - mean * mean;
        float rs = rsqrtf(var + BN_EPS);
        a[t] = g[t] * rs;
        c[t] = beta[t] - mean * a[t];
    }
    __syncthreads();
    for (int idx = t; idx < 64 * 64; idx += blockDim.x)
        Wf[idx] = a[idx >> 6] * Wn[idx];
    if (t < 64) {
        float s = add_bn ? bn[t] : 0.0f;
#pragma unroll 8
        for (int k = 0; k < 64; k++) s += c[k] * Wn[k * 64 + t];
        bf[t] = s;
    }
}

__global__ void fold3_k(const float* __restrict__ stats, const float* __restrict__ g,
                        const float* __restrict__ beta, const float* __restrict__ w2,
                        const float* __restrict__ b2, float* __restrict__ wfbf) {
    __shared__ float cw[64];
    int t = threadIdx.x;
    float mean = stats[t] * (1.0f / NN);
    float var = stats[64 + t] * (1.0f / NN) - mean * mean;
    float rs = rsqrtf(var + BN_EPS);
    float a = g[t] * rs;
    float c = beta[t] - mean * a;
    wfbf[t] = a * w2[t];
    cw[t] = c * w2[t];
    __syncthreads();
    if (t == 0) {
        float s = b2[0];
        for (int k = 0; k < 64; k++) s += cw[k];
        wfbf[64] = s;
    }
}

// One warp per node: out[i] = dot64(z[i], wf) + bf
__global__ void final_k(const float* __restrict__ z, const float* __restrict__ wfbf,
                        float* __restrict__ out, int n) {
    int warp = (blockIdx.x * blockDim.x + threadIdx.x) >> 5;
    int lane = threadIdx.x & 31;
    if (warp >= n) return;
    float2 v = ((const float2*)z)[warp * 32 + lane];
    float2 w = ((const float2*)wfbf)[lane];
    float s = v.x * w.x + v.y * w.y;
#pragma unroll
    for (int o = 16; o; o >>= 1) s += __shfl_down_sync(0xFFFFFFFFu, s, o);
    if (lane == 0) out[warp] = s + wfbf[64];
}

// ---------------- host launcher ----------------
extern "C" void kernel_launch(void* const* d_in, const int* in_sizes, int n_in,
                              void* d_out, int out_size) {
    const float* x       = (const float*)d_in[0];
    const float* ew      = (const float*)d_in[1];
    const float* W1      = (const float*)d_in[2];
    const float* b1      = (const float*)d_in[3];
    const float* W2      = (const float*)d_in[4];
    const float* lin1_W  = (const float*)d_in[6];
    const float* lin1_b  = (const float*)d_in[7];
    const float* lin2_W  = (const float*)d_in[8];
    const float* lin2_b  = (const float*)d_in[9];
    const float* bn1_g   = (const float*)d_in[10];
    const float* bn1_b   = (const float*)d_in[11];
    const float* bn2_g   = (const float*)d_in[12];
    const float* bn2_b   = (const float*)d_in[13];
    const float* bn3_g   = (const float*)d_in[14];
    const float* bn3_b   = (const float*)d_in[15];
    const int*   ei      = (const int*)d_in[16];     // int32
    float* out           = (float*)d_out;

    float *deg, *buf1, *buf2, *stats, *W2f, *cb2, *W3f, *d3, *wfbf;
    int *cnt, *rowptr, *cursor, *bsum, *boff;
    int2 *edges;
    __half *bufh;
    cudaGetSymbolAddress((void**)&deg,    g_deg);
    cudaGetSymbolAddress((void**)&cnt,    g_cnt);
    cudaGetSymbolAddress((void**)&rowptr, g_rowptr);
    cudaGetSymbolAddress((void**)&cursor, g_cursor);
    cudaGetSymbolAddress((void**)&bsum,   g_bsum);
    cudaGetSymbolAddress((void**)&boff,   g_boff);
    cudaGetSymbolAddress((void**)&edges,  g_edges);
    cudaGetSymbolAddress((void**)&bufh,   g_bufh);
    cudaGetSymbolAddress((void**)&buf1,   g_buf1);
    cudaGetSymbolAddress((void**)&buf2,   g_buf2);
    cudaGetSymbolAddress((void**)&stats,  g_stats);
    cudaGetSymbolAddress((void**)&W2f,    g_W2f);
    cudaGetSymbolAddress((void**)&cb2,    g_cb2);
    cudaGetSymbolAddress((void**)&W3f,    g_W3f);
    cudaGetSymbolAddress((void**)&d3,     g_d3);
    cudaGetSymbolAddress((void**)&wfbf,   g_wfbf);

    static cudaStream_t s2 = nullptr;
    static cudaEvent_t evA = nullptr, evB = nullptr;
    if (!s2) {
        cudaStreamCreateWithFlags(&s2, cudaStreamNonBlocking);
        cudaEventCreateWithFlags(&evA, cudaEventDisableTiming);
        cudaEventCreateWithFlags(&evB, cudaEventDisableTiming);
    }

    const int TPB = 256;
    const int gNode  = (NN + TPB - 1) / TPB;
    const int gEdge  = (EE + TPB - 1) / TPB;
    const int gGemm  = (NN + 63) / 64;
    const int nwarps = GBLK * GW;
    const int npw    = (NN + nwarps - 1) / nwarps;   // nodes per warp (13)

    // fork: gemm1 on side stream, graph prep on main stream
    cudaEventRecord(evA, 0);
    cudaStreamWaitEvent(s2, evA, 0);
    gemm_k<128, true><<<gGemm, TPB, 0, s2>>>(x, W1, nullptr, nullptr, bufh, nullptr, NN);
    cudaEventRecord(evB, s2);

    init_k<<<gNode, TPB>>>(deg, cnt, stats);
    deghist_k<<<gEdge, TPB>>>(ei, ew, deg, cnt);
    scan1_k<<<NSCAN, 1024>>>(cnt, rowptr, bsum);
    scan2_k<<<1, 32>>>(bsum, boff, rowptr);
    scan3_k<<<gNode, TPB>>>(rowptr, boff, cursor);
    fill_k<<<gEdge, TPB>>>(ei, ew, deg, cursor, edges);

    cudaStreamWaitEvent(0, evB, 0);

    // layer 1
    gather_k<<<GBLK, GW * 32>>>((const __half2*)bufh, rowptr, edges, deg, b1,
                                (float2*)buf2, stats + 0, 1, npw);
    fold_k<<<1, 256>>>(stats + 0, bn1_g, bn1_b, W2, nullptr, W2f, cb2, 0);

    // layer 2
    gemm_k<64, true><<<gGemm, TPB>>>(buf2, W2f, cb2, nullptr, bufh, nullptr, NN);
    gather_k<<<GBLK, GW * 32>>>((const __half2*)bufh, rowptr, edges, deg, nullptr,
                                (float2*)buf2, stats + 128, 0, npw);
    fold_k<<<1, 256>>>(stats + 128, bn2_g, bn2_b, lin1_W, lin1_b, W3f, d3, 1);

    // lin1 (+bn2) with fused BN3 stats, then bn3+lin2 folded dot
    gemm_k<64, false><<<gGemm, TPB>>>(buf2, W3f, d3, buf1, nullptr, stats + 256, NN);
    fold3_k<<<1, 64>>>(stats + 256, bn3_g, bn3_b, lin2_W, lin2_b, wfbf);
    final_k<<<(NN * 32 + TPB - 1) / TPB, TPB>>>(buf1, wfbf, out, NN);
}

// round 17
// speedup vs baseline: 1.2551x; 1.2551x over previous
#include <cuda_runtime.h>
#include <cuda_fp16.h>
#include <cstdint>

#define NN 100000
#define EE 3200000
#define HD 64
#define BN_EPS 1e-5f
#define NSCAN ((NN + 1023) / 1024)   // 98 scan blocks
#define GW 4                          // warps per gather block
#define GBLK 888                      // 6 blocks/SM -> 3552 warps

// ---------------- scratch (device globals; no allocation allowed) ----------------
__device__ float g_deg[NN];
__device__ int   g_cnt[NN];
__device__ int   g_rowptr[NN + 1];
__device__ int   g_cursor[NN];
__device__ int   g_bsum[NSCAN];
__device__ int   g_boff[NSCAN];
__device__ __align__(8)  int2   g_edges[EE];     // {src*128 byte-offset, coef_bits}
__device__ __align__(16) __half g_bufh[NN * HD];  // gemm outputs (gather input)
__device__ __align__(16) __half g_bufh2[NN * HD]; // gather outputs (gemm input)
__device__ __align__(16) float  g_buf1[NN * HD];  // lin1 fp32 output
__device__ float g_stats[6 * HD];
__device__ __align__(16) __half g_W2f[HD * HD];
__device__ float g_cb2[HD];
__device__ __align__(16) __half g_W3f[HD * HD];
__device__ float g_d3[HD];
__device__ __align__(16) float g_wfbf[HD + 4];

__device__ __forceinline__ unsigned pack_h2(__half a, __half b) {
    __half2 h = __halves2half2(a, b);
    return *(unsigned*)&h;
}

// ---------------- graph prep ----------------

__global__ void init_k(float* deg, int* cnt, float* stats) {
    int i = blockIdx.x * blockDim.x + threadIdx.x;
    if (i < NN) { deg[i] = 1.0f; cnt[i] = 0; }
    if (i < 6 * HD) stats[i] = 0.0f;
}

__global__ void deghist_k(const int* __restrict__ ei, const float* __restrict__ ew,
                          float* deg, int* cnt) {
    int e = blockIdx.x * blockDim.x + threadIdx.x;
    if (e >= EE) return;
    int d = ei[EE + e];
    atomicAdd(&deg[d], ew[e]);
    atomicAdd(&cnt[d], 1);
}

__global__ void scan1_k(const int* __restrict__ cnt, int* rowptr, int* bsum) {
    __shared__ int sh[1024];
    int t = threadIdx.x;
    int i = blockIdx.x * 1024 + t;
    int c = (i < NN) ? cnt[i] : 0;
    sh[t] = c;
    __syncthreads();
#pragma unroll
    for (int off = 1; off < 1024; off <<= 1) {
        int v = (t >= off) ? sh[t - off] : 0;
        __syncthreads();
        sh[t] += v;
        __syncthreads();
    }
    if (i < NN) rowptr[i] = sh[t] - c;
    if (t == 1023) bsum[blockIdx.x] = sh[t];
}

__global__ void scan2_k(const int* __restrict__ bsum, int* boff, int* rowptr) {
    int lane = threadIdx.x;
    int run = 0;
    for (int b0 = 0; b0 < NSCAN; b0 += 32) {
        int idx = b0 + lane;
        int c = (idx < NSCAN) ? bsum[idx] : 0;
        int v = c;
#pragma unroll
        for (int off = 1; off < 32; off <<= 1) {
            int t = __shfl_up_sync(0xFFFFFFFFu, v, off);
            if (lane >= off) v += t;
        }
        if (idx < NSCAN) boff[idx] = run + v - c;
        run += __shfl_sync(0xFFFFFFFFu, v, 31);
    }
    if (lane == 0) rowptr[NN] = EE;
}

__global__ void scan3_k(int* rowptr, const int* __restrict__ boff, int* cursor) {
    int i = blockIdx.x * blockDim.x + threadIdx.x;
    if (i >= NN) return;
    int v = rowptr[i] + boff[i >> 10];
    rowptr[i] = v;
    cursor[i] = v;
}

__global__ void fill_k(const int* __restrict__ ei, const float* __restrict__ ew,
                       const float* __restrict__ deg, int* cursor, int2* edges) {
    int e = blockIdx.x * blockDim.x + threadIdx.x;
    if (e >= EE) return;
    int s = ei[e];
    int d = ei[EE + e];
    float cf = ew[e] * rsqrtf(deg[s]) * rsqrtf(deg[d]);
    int pos = atomicAdd(&cursor[d], 1);
    edges[pos] = make_int2(s * 128, __float_as_int(cf));
}

// ---------------- fp32 GEMM (gemm1 only; hidden under graph prep) ----------------
template <int K>
__global__ void gemm_k(const float* __restrict__ A, const float* __restrict__ W,
                       __half* __restrict__ Ch, int n) {
    constexpr int TM = 64;
    constexpr int KC = 64;
    __shared__ float As[KC][TM + 4];
    __shared__ float Ws[KC][64];
    const int tid = threadIdx.x;
    const int tx = tid & 15;
    const int ty = tid >> 4;
    const int m_base = blockIdx.x * TM;

    float acc[4][4] = {};

    for (int kk = 0; kk < K; kk += KC) {
        for (int idx = tid; idx < TM * KC; idx += 256) {
            int m = idx / KC, k = idx % KC;
            int row = m_base + m;
            As[k][m] = (row < n) ? A[row * K + kk + k] : 0.0f;
        }
        for (int idx = tid; idx < KC * 64; idx += 256) {
            int k = idx >> 6, c = idx & 63;
            Ws[k][c] = W[(kk + k) * 64 + c];
        }
        __syncthreads();
#pragma unroll 16
        for (int k = 0; k < KC; k++) {
            float4 a = *(const float4*)&As[k][ty * 4];
            float4 b = *(const float4*)&Ws[k][tx * 4];
            float av[4] = {a.x, a.y, a.z, a.w};
            float bv[4] = {b.x, b.y, b.z, b.w};
#pragma unroll
            for (int i = 0; i < 4; i++)
#pragma unroll
                for (int j = 0; j < 4; j++)
                    acc[i][j] += av[i] * bv[j];
        }
        __syncthreads();
    }

#pragma unroll
    for (int i = 0; i < 4; i++) {
        int row = m_base + ty * 4 + i;
        if (row >= n) break;
        __half2* p = (__half2*)&Ch[row * 64 + tx * 4];
        p[0] = __float22half2_rn(make_float2(acc[i][0], acc[i][1]));
        p[1] = __float22half2_rn(make_float2(acc[i][2], acc[i][3]));
    }
}

// ---------------- HMMA GEMM: C[n,64] = A_half[n,64] @ W_half[64,64] ----------------
// 256 thr / 8 warps; warp w: mtile = w>>1 (16 rows), nhalf = w&1 (32 cols).
// HOUT: half output; else fp32 output + fused BN stats.
template <bool HOUT>
__global__ void __launch_bounds__(256)
mgemm_k(const __half* __restrict__ A, const __half* __restrict__ W,
        const float* __restrict__ bias, __half* __restrict__ Ch,
        float* __restrict__ C, float* __restrict__ stats, int n) {
    __shared__ __align__(16) __half As[64][72];   // stride 72 halves: conflict-free frags
    __shared__ __align__(16) __half Wsm[64][64];
    __shared__ float sred[2][4][64];

    const int tid  = threadIdx.x;
    const int lane = tid & 31;
    const int w    = tid >> 5;
    const int mt   = w >> 1;
    const int wn   = w & 1;
    const int m0   = mt * 16;
    const int n0   = wn * 32;
    const int m_base = blockIdx.x * 64;

    // load W (8KB) and A tile (rows m_base..+63)
    {
        const uint4* Wg = (const uint4*)W;
        uint4* Ws4 = (uint4*)&Wsm[0][0];
        Ws4[tid] = Wg[tid];
        Ws4[tid + 256] = Wg[tid + 256];
        for (int idx = tid; idx < 64 * 8; idx += 256) {   // 8 uint4 per row
            int row = idx >> 3, seg = idx & 7;
            uint4 v = make_uint4(0, 0, 0, 0);
            int gr = m_base + row;
            if (gr < n) v = ((const uint4*)&A[gr * 64])[seg];
            ((uint4*)&As[row][0])[seg] = v;
        }
    }
    __syncthreads();

    // preload B fragments (per-thread, from Wsm)
    unsigned bf[4][4][2];
    {
        int g  = lane >> 2;
        int kq = (lane & 3) * 2;
#pragma unroll
        for (int nt = 0; nt < 4; nt++) {
            int ncol = n0 + nt * 8 + g;
#pragma unroll
            for (int ks = 0; ks < 4; ks++) {
                int k = ks * 16 + kq;
                bf[nt][ks][0] = pack_h2(Wsm[k][ncol], Wsm[k + 1][ncol]);
                bf[nt][ks][1] = pack_h2(Wsm[k + 8][ncol], Wsm[k + 9][ncol]);
            }
        }
    }

    float c[4][4] = {};
    {
        int row = m0 + (lane >> 2);
        int kq  = (lane & 3) * 2;
#pragma unroll
        for (int ks = 0; ks < 4; ks++) {
            int kx = ks * 16 + kq;
            unsigned a0 = *(const unsigned*)&As[row][kx];
            unsigned a1 = *(const unsigned*)&As[row + 8][kx];
            unsigned a2 = *(const unsigned*)&As[row][kx + 8];
            unsigned a3 = *(const unsigned*)&As[row + 8][kx + 8];
#pragma unroll
            for (int nt = 0; nt < 4; nt++) {
                asm volatile(
                    "mma.sync.aligned.m16n8k16.row.col.f32.f16.f16.f32 "
                    "{%0,%1,%2,%3}, {%4,%5,%6,%7}, {%8,%9}, {%0,%1,%2,%3};"
                    : "+f"(c[nt][0]), "+f"(c[nt][1]), "+f"(c[nt][2]), "+f"(c[nt][3])
                    : "r"(a0), "r"(a1), "r"(a2), "r"(a3),
                      "r"(bf[nt][ks][0]), "r"(bf[nt][ks][1]));
            }
        }
    }

    // epilogue
    int g = lane >> 2;
    int rowA = m_base + m0 + g;
    int rowB = rowA + 8;
    bool okA = rowA < n, okB = rowB < n;
#pragma unroll
    for (int nt = 0; nt < 4; nt++) {
        int col = n0 + nt * 8 + (lane & 3) * 2;
        float b0 = bias[col], b1 = bias[col + 1];
        float v0 = okA ? c[nt][0] + b0 : 0.f;
        float v1 = okA ? c[nt][1] + b1 : 0.f;
        float v2 = okB ? c[nt][2] + b0 : 0.f;
        float v3 = okB ? c[nt][3] + b1 : 0.f;
        c[nt][0] = v0; c[nt][1] = v1; c[nt][2] = v2; c[nt][3] = v3;
        if (HOUT) {
            if (okA) *(__half2*)&Ch[rowA * 64 + col] = __float22half2_rn(make_float2(v0, v1));
            if (okB) *(__half2*)&Ch[rowB * 64 + col] = __float22half2_rn(make_float2(v2, v3));
        } else {
            if (okA) *(float2*)&C[rowA * 64 + col] = make_float2(v0, v1);
            if (okB) *(float2*)&C[rowB * 64 + col] = make_float2(v2, v3);
        }
    }

    if (!HOUT) {   // fused BN stats
#pragma unroll
        for (int nt = 0; nt < 4; nt++) {
            float s0 = c[nt][0] + c[nt][2];
            float s1 = c[nt][1] + c[nt][3];
            float q0 = c[nt][0] * c[nt][0] + c[nt][2] * c[nt][2];
            float q1 = c[nt][1] * c[nt][1] + c[nt][3] * c[nt][3];
#pragma unroll
            for (int off = 4; off <= 16; off <<= 1) {
                s0 += __shfl_xor_sync(0xFFFFFFFFu, s0, off);
                s1 += __shfl_xor_sync(0xFFFFFFFFu, s1, off);
                q0 += __shfl_xor_sync(0xFFFFFFFFu, q0, off);
                q1 += __shfl_xor_sync(0xFFFFFFFFu, q1, off);
            }
            if (lane < 4) {
                int col = n0 + nt * 8 + lane * 2;
                sred[0][mt][col] = s0;
                sred[0][mt][col + 1] = s1;
                sred[1][mt][col] = q0;
                sred[1][mt][col + 1] = q1;
            }
        }
        __syncthreads();
        if (tid < 64) {
            float s = 0.f, q = 0.f;
#pragma unroll
            for (int r = 0; r < 4; r++) { s += sred[0][r][tid]; q += sred[1][r][tid]; }
            atomicAdd(&stats[tid], s);
            atomicAdd(&stats[64 + tid], q);
        }
    }
}

// ---------------- edge-stream gather, double-buffered cp.async (R14 config) -------
__global__ void __launch_bounds__(GW * 32)
gather_k(const __half2* __restrict__ inh, const int* __restrict__ rowptr,
         const int2* __restrict__ edges, const float* __restrict__ deg,
         const float* __restrict__ bias, __half2* __restrict__ outh,
         float* __restrict__ stats, int relu, int npw) {
    __shared__ __align__(16) char rb[GW][2][32 * 128];
    __shared__ float cfb[GW][2][32];

    const int w    = threadIdx.x >> 5;
    const int lane = threadIdx.x & 31;
    const int warp = (blockIdx.x * blockDim.x + threadIdx.x) >> 5;

    float s0 = 0.f, q0 = 0.f, s1 = 0.f, q1 = 0.f;
    const int n0 = warp * npw;

    if (n0 < NN) {
        const int n1 = min(NN, n0 + npw);
        const int estart = __ldg(&rowptr[n0]);
        const int eend   = __ldg(&rowptr[n1]);
        const int nch    = (eend - estart + 31) >> 5;

        float2 bv = relu ? ((const float2*)bias)[lane] : make_float2(0.f, 0.f);
        const char* inb = (const char*)inh;
        unsigned int rbs0 = (unsigned int)__cvta_generic_to_shared(&rb[w][0][0]);
        unsigned int rbs1 = (unsigned int)__cvta_generic_to_shared(&rb[w][1][0]);

        auto stage = [&](int c, int b) {
            int e = estart + c * 32 + lane;
            int2 p = make_int2(0, 0);
            if (e < eend) p = __ldg(&edges[e]);
            cfb[w][b][lane] = __int_as_float(p.y);
            unsigned int dstb = b ? rbs1 : rbs0;
#pragma unroll
            for (int j = 0; j < 8; j++) {
                int seg = j * 32 + lane;
                int row = seg >> 3;
                int ss  = seg & 7;
                int off = __shfl_sync(0xFFFFFFFFu, p.x, row);
                const char* src = inb + off + ss * 16;
                unsigned int dst = dstb + row * 128 + ss * 16;
                asm volatile("cp.async.cg.shared.global [%0], [%1], 16;"
                             :: "r"(dst), "l"(src));
            }
            asm volatile("cp.async.commit_group;");
        };

        int i = n0;
        int end = __ldg(&rowptr[i + 1]);
        float inv = __fdividef(1.0f, deg[i]);
        float2 sf = __half22float2(inh[i * 32 + lane]);
        float2 acc = make_float2(sf.x * inv, sf.y * inv);

        auto flush = [&](int node) {
            float2 o = acc;
            if (relu) {
                o.x = fmaxf(o.x + bv.x, 0.f);
                o.y = fmaxf(o.y + bv.y, 0.f);
            }
            outh[node * 32 + lane] = __float22half2_rn(o);
            s0 += o.x; q0 += o.x * o.x;
            s1 += o.y; q1 += o.y * o.y;
        };
        auto initnode = [&](int node) {
            float iv = __fdividef(1.0f, deg[node]);
            float2 s = __half22float2(inh[node * 32 + lane]);
            acc = make_float2(s.x * iv, s.y * iv);
        };

        if (nch > 0) stage(0, 0);
        for (int c = 0; c < nch; c++) {
            if (c + 1 < nch) {
                stage(c + 1, (c + 1) & 1);
                asm volatile("cp.async.wait_group 1;");
            } else {
                asm volatile("cp.async.wait_group 0;");
            }
            __syncwarp();
            int b = c & 1;
            int base = estart + c * 32;
            const char* rbc = &rb[w][b][0];
            const float* cfc = &cfb[w][b][0];
#pragma unroll 8
            for (int k = 0; k < 32; k++) {
                int eg = base + k;
                while (eg >= end && i + 1 < n1) {
                    flush(i);
                    i++;
                    initnode(i);
                    end = __ldg(&rowptr[i + 1]);
                }
                float cf = cfc[k];
                __half2 hv = *(const __half2*)(rbc + k * 128 + lane * 4);
                float2 v = __half22float2(hv);
                acc.x += cf * v.x;
                acc.y += cf * v.y;
            }
            __syncwarp();
        }
        flush(i);
        for (int j = i + 1; j < n1; j++) { initnode(j); flush(j); }
    }

    atomicAdd(&stats[2 * lane],          s0);
    atomicAdd(&stats[2 * lane + 1],      s1);
    atomicAdd(&stats[64 + 2 * lane],     q0);
    atomicAdd(&stats[64 + 2 * lane + 1], q1);
}

// ---------------- BN folds (weights emitted as half) ----------------
__global__ void fold_k(const float* __restrict__ stats, const float* __restrict__ g,
                       const float* __restrict__ beta, const float* __restrict__ Wn,
                       const float* __restrict__ bn, __half* __restrict__ Wf,
                       float* __restrict__ bf, int add_bn) {
    __shared__ float a[64], c[64];
    int t = threadIdx.x;
    if (t < 64) {
        float mean = stats[t] * (1.0f / NN);
        float var = stats[64 + t] * (1.0f / NN) - mean * mean;
        float rs = rsqrtf(var + BN_EPS);
        a[t] = g[t] * rs;
        c[t] = beta[t] - mean * a[t];
    }
    __syncthreads();
    for (int idx = t; idx < 64 * 64; idx += blockDim.x)
        Wf[idx] = __float2half(a[idx >> 6] * Wn[idx]);
    if (t < 64) {
        float s = add_bn ? bn[t] : 0.0f;
#pragma unroll 8
        for (int k = 0; k < 64; k++) s += c[k] * Wn[k * 64 + t];
        bf[t] = s;
    }
}

__global__ void fold3_k(const float* __restrict__ stats, const float* __restrict__ g,
                        const float* __restrict__ beta, const float* __restrict__ w2,
                        const float* __restrict__ b2, float* __restrict__ wfbf) {
    __shared__ float cw[64];
    int t = threadIdx.x;
    float mean = stats[t] * (1.0f / NN);
    float var = stats[64 + t] * (1.0f / NN) - mean * mean;
    float rs = rsqrtf(var + BN_EPS);
    float a = g[t] * rs;
    float c = beta[t] - mean * a;
    wfbf[t] = a * w2[t];
    cw[t] = c * w2[t];
    __syncthreads();
    if (t == 0) {
        float s = b2[0];
        for (int k = 0; k < 64; k++) s += cw[k];
        wfbf[64] = s;
    }
}

// One warp per node: out[i] = dot64(z[i], wf) + bf
__global__ void final_k(const float* __restrict__ z, const float* __restrict__ wfbf,
                        float* __restrict__ out, int n) {
    int warp = (blockIdx.x * blockDim.x + threadIdx.x) >> 5;
    int lane = threadIdx.x & 31;
    if (warp >= n) return;
    float2 v = ((const float2*)z)[warp * 32 + lane];
    float2 w = ((const float2*)wfbf)[lane];
    float s = v.x * w.x + v.y * w.y;
#pragma unroll
    for (int o = 16; o; o >>= 1) s += __shfl_down_sync(0xFFFFFFFFu, s, o);
    if (lane == 0) out[warp] = s + wfbf[64];
}

// ---------------- host launcher ----------------
extern "C" void kernel_launch(void* const* d_in, const int* in_sizes, int n_in,
                              void* d_out, int out_size) {
    const float* x       = (const float*)d_in[0];
    const float* ew      = (const float*)d_in[1];
    const float* W1      = (const float*)d_in[2];
    const float* b1      = (const float*)d_in[3];
    const float* W2      = (const float*)d_in[4];
    const float* lin1_W  = (const float*)d_in[6];
    const float* lin1_b  = (const float*)d_in[7];
    const float* lin2_W  = (const float*)d_in[8];
    const float* lin2_b  = (const float*)d_in[9];
    const float* bn1_g   = (const float*)d_in[10];
    const float* bn1_b   = (const float*)d_in[11];
    const float* bn2_g   = (const float*)d_in[12];
    const float* bn2_b   = (const float*)d_in[13];
    const float* bn3_g   = (const float*)d_in[14];
    const float* bn3_b   = (const float*)d_in[15];
    const int*   ei      = (const int*)d_in[16];     // int32
    float* out           = (float*)d_out;

    float *deg, *buf1, *stats, *cb2, *d3, *wfbf;
    int *cnt, *rowptr, *cursor, *bsum, *boff;
    int2 *edges;
    __half *bufh, *bufh2, *W2f, *W3f;
    cudaGetSymbolAddress((void**)&deg,    g_deg);
    cudaGetSymbolAddress((void**)&cnt,    g_cnt);
    cudaGetSymbolAddress((void**)&rowptr, g_rowptr);
    cudaGetSymbolAddress((void**)&cursor, g_cursor);
    cudaGetSymbolAddress((void**)&bsum,   g_bsum);
    cudaGetSymbolAddress((void**)&boff,   g_boff);
    cudaGetSymbolAddress((void**)&edges,  g_edges);
    cudaGetSymbolAddress((void**)&bufh,   g_bufh);
    cudaGetSymbolAddress((void**)&bufh2,  g_bufh2);
    cudaGetSymbolAddress((void**)&buf1,   g_buf1);
    cudaGetSymbolAddress((void**)&stats,  g_stats);
    cudaGetSymbolAddress((void**)&W2f,    g_W2f);
    cudaGetSymbolAddress((void**)&cb2,    g_cb2);
    cudaGetSymbolAddress((void**)&W3f,    g_W3f);
    cudaGetSymbolAddress((void**)&d3,     g_d3);
    cudaGetSymbolAddress((void**)&wfbf,   g_wfbf);

    static cudaStream_t s2 = nullptr;
    static cudaEvent_t evA = nullptr, evB = nullptr;
    if (!s2) {
        cudaStreamCreateWithFlags(&s2, cudaStreamNonBlocking);
        cudaEventCreateWithFlags(&evA, cudaEventDisableTiming);
        cudaEventCreateWithFlags(&evB, cudaEventDisableTiming);
    }

    const int TPB = 256;
    const int gNode  = (NN + TPB - 1) / TPB;
    const int gEdge  = (EE + TPB - 1) / TPB;
    const int gGemm  = (NN + 63) / 64;
    const int nwarps = GBLK * GW;
    const int npw    = (NN + nwarps - 1) / nwarps;   // nodes per warp (29)

    // fork: gemm1 on side stream, graph prep on main stream
    cudaEventRecord(evA, 0);
    cudaStreamWaitEvent(s2, evA, 0);
    gemm_k<128><<<gGemm, TPB, 0, s2>>>(x, W1, bufh, NN);
    cudaEventRecord(evB, s2);

    init_k<<<gNode, TPB>>>(deg, cnt, stats);
    deghist_k<<<gEdge, TPB>>>(ei, ew, deg, cnt);
    scan1_k<<<NSCAN, 1024>>>(cnt, rowptr, bsum);
    scan2_k<<<1, 32>>>(bsum, boff, rowptr);
    scan3_k<<<gNode, TPB>>>(rowptr, boff, cursor);
    fill_k<<<gEdge, TPB>>>(ei, ew, deg, cursor, edges);

    cudaStreamWaitEvent(0, evB, 0);

    // layer 1: gather(x@W1) -> bufh2 (half); bn1 folded into W2 (half)
    gather_k<<<GBLK, GW * 32>>>((const __half2*)bufh, rowptr, edges, deg, b1,
                                (__half2*)bufh2, stats + 0, 1, npw);
    fold_k<<<1, 256>>>(stats + 0, bn1_g, bn1_b, W2, nullptr, W2f, cb2, 0);

    // layer 2: HMMA gemm2 -> bufh (half), gather -> bufh2; bn2 folded into lin1
    mgemm_k<true><<<gGemm, TPB>>>(bufh2, W2f, cb2, bufh, nullptr, nullptr, NN);
    gather_k<<<GBLK, GW * 32>>>((const __half2*)bufh, rowptr, edges, deg, nullptr,
                                (__half2*)bufh2, stats + 128, 0, npw);
    fold_k<<<1, 256>>>(stats + 128, bn2_g, bn2_b, lin1_W, lin1_b, W3f, d3, 1);

    // lin1 (HMMA, +bn2, fused BN3 stats) -> buf1 fp32; bn3+lin2 folded dot
    mgemm_k<false><<<gGemm, TPB>>>(bufh2, W3f, d3, nullptr, buf1, stats + 256, NN);
    fold3_k<<<1, 64>>>(stats + 256, bn3_g, bn3_b, lin2_W, lin2_b, wfbf);
    final_k<<<(NN * 32 + TPB - 1) / TPB, TPB>>>(buf1, wfbf, out, NN);
}